// round 3
// baseline (speedup 1.0000x reference)
#include <cuda_runtime.h>

#define DIM 64
#define MAX_NODES 100000
#define MAX_EDGES 1600000
#define SCAN_BS 1024

typedef unsigned long long ull;

// ---- device scratch (no allocs allowed) ----
__device__ __align__(16) float g_h[MAX_NODES * DIM];     // h = x + aggr
__device__ int  g_cnt[MAX_NODES];                        // degree histogram
__device__ int  g_offpart[MAX_NODES];                    // per-block exclusive scan
__device__ int  g_bsum[256];                             // block sums for scan
__device__ int  g_off[MAX_NODES + 1];                    // final offsets
__device__ int  g_cur[MAX_NODES];                        // scatter cursors
__device__ __align__(8) int2 g_edges[MAX_EDGES];         // (src, edge_id) sorted by dst

__device__ __forceinline__ ull pk2(float lo, float hi) {
    ull r; asm("mov.b64 %0, {%1, %2};" : "=l"(r) : "f"(lo), "f"(hi)); return r;
}
__device__ __forceinline__ void upk2(float& lo, float& hi, ull v) {
    asm("mov.b64 {%0, %1}, %2;" : "=f"(lo), "=f"(hi) : "l"(v));
}
__device__ __forceinline__ void ffma2(ull& d, ull a, ull b) {
    asm("fma.rn.f32x2 %0, %1, %2, %0;" : "+l"(d) : "l"(a), "l"(b));
}

// ---------------------------------------------------------------------------
// Phase A: dst-bucket construction (counting sort, int atomics only)
// ---------------------------------------------------------------------------
__global__ void zero_cnt_kernel(int N) {
    int i = blockIdx.x * blockDim.x + threadIdx.x;
    if (i < N) g_cnt[i] = 0;
}

__global__ void hist_kernel(const int* __restrict__ ei, int E) {
    int e = blockIdx.x * blockDim.x + threadIdx.x;
    if (e < E) atomicAdd(&g_cnt[ei[E + e]], 1);
}

// per-block exclusive scan of counts; block total -> g_bsum
__global__ void __launch_bounds__(SCAN_BS) scan1_kernel(int N) {
    const int tid = threadIdx.x;
    const int lane = tid & 31, wid = tid >> 5;
    const int i = blockIdx.x * SCAN_BS + tid;
    int c = (i < N) ? g_cnt[i] : 0;

    int v = c;
#pragma unroll
    for (int d = 1; d < 32; d <<= 1) {
        int t = __shfl_up_sync(0xFFFFFFFFu, v, d);
        if (lane >= d) v += t;
    }
    __shared__ int ws[32];
    if (lane == 31) ws[wid] = v;
    __syncthreads();
    if (wid == 0) {
        int s = ws[lane];
#pragma unroll
        for (int d = 1; d < 32; d <<= 1) {
            int t = __shfl_up_sync(0xFFFFFFFFu, s, d);
            if (lane >= d) s += t;
        }
        ws[lane] = s;
    }
    __syncthreads();
    const int base = (wid > 0) ? ws[wid - 1] : 0;
    const int incl = v + base;
    if (i < N) g_offpart[i] = incl - c;
    if (tid == SCAN_BS - 1) g_bsum[blockIdx.x] = incl;
}

// scan of block sums (tiny: <=256 entries, sequential)
__global__ void scan2_kernel(int nb) {
    if (threadIdx.x == 0 && blockIdx.x == 0) {
        int s = 0;
        for (int b = 0; b < nb; b++) { int t = g_bsum[b]; g_bsum[b] = s; s += t; }
    }
}

// apply block offsets -> final offsets + cursors
__global__ void __launch_bounds__(SCAN_BS) scan3_kernel(int N, int E) {
    const int i = blockIdx.x * SCAN_BS + threadIdx.x;
    if (i < N) {
        const int o = g_offpart[i] + g_bsum[blockIdx.x];
        g_off[i] = o;
        g_cur[i] = o;
    }
    if (blockIdx.x == 0 && threadIdx.x == 0) g_off[N] = E;
}

__global__ void scatter_kernel(const int* __restrict__ ei, int E) {
    int e = blockIdx.x * blockDim.x + threadIdx.x;
    if (e < E) {
        const int dst = ei[E + e];
        const int p = atomicAdd(&g_cur[dst], 1);
        g_edges[p] = make_int2(ei[e], e);
    }
}

// ---------------------------------------------------------------------------
// Phase B: per-node aggregation. One warp per node, lane owns cols (2l, 2l+1).
// h[n] = x[n] + sum_{e: dst=n} relu(x[src_e] + ea_e @ We + be)
// Register accumulation, no fp32 atomics. Next-edge records + edge_attr
// prefetched inside the loop (software pipeline).
// ---------------------------------------------------------------------------
__global__ void __launch_bounds__(256) aggregate_kernel(
    const float* __restrict__ x,
    const float4* __restrict__ ea4,     // [E, 16] as float4
    const float* __restrict__ We,       // [16, 64]
    const float* __restrict__ be,       // [64]
    int N)
{
    __shared__ ull Wp[8 * DIM];         // packed K-pairs of We: Wp[k2*64+j]
    const int tid = threadIdx.x;
    for (int f = tid; f < 8 * DIM; f += 256) {
        const int k2 = f >> 6, j = f & 63;
        Wp[f] = pk2(We[(2 * k2) * DIM + j], We[(2 * k2 + 1) * DIM + j]);
    }
    __syncthreads();

    const int lane = tid & 31;
    const int c0 = lane * 2;
    const int n = (blockIdx.x * blockDim.x + tid) >> 5;
    if (n >= N) return;

    ull wA[8], wB[8];
#pragma unroll
    for (int k2 = 0; k2 < 8; k2++) {
        wA[k2] = Wp[k2 * 64 + c0];
        wB[k2] = Wp[k2 * 64 + c0 + 1];
    }
    const float2 bev = *reinterpret_cast<const float2*>(be + c0);

    const int beg = g_off[n];
    const int end = g_off[n + 1];

    float acc0 = 0.f, acc1 = 0.f;

    int p = beg;
    int2 er = make_int2(0, 0);
    float4 q0, q1, q2, q3;
    if (p < end) {
        er = g_edges[p];
        const float4* ep = ea4 + (size_t)er.y * 4;
        q0 = ep[0]; q1 = ep[1]; q2 = ep[2]; q3 = ep[3];
    }
    while (p < end) {
        const int pn = p + 1;
        int2 ern = make_int2(0, 0);
        if (pn < end) ern = g_edges[pn];

        // issue this edge's x gather early (long-latency)
        const float2 xv = *reinterpret_cast<const float2*>(x + (size_t)er.x * DIM + c0);

        // prefetch next edge_attr
        float4 n0, n1, n2, n3;
        n0 = n1 = n2 = n3 = make_float4(0.f, 0.f, 0.f, 0.f);
        if (pn < end) {
            const float4* ep = ea4 + (size_t)ern.y * 4;
            n0 = ep[0]; n1 = ep[1]; n2 = ep[2]; n3 = ep[3];
        }

        ull a[8];
        a[0] = pk2(q0.x, q0.y); a[1] = pk2(q0.z, q0.w);
        a[2] = pk2(q1.x, q1.y); a[3] = pk2(q1.z, q1.w);
        a[4] = pk2(q2.x, q2.y); a[5] = pk2(q2.z, q2.w);
        a[6] = pk2(q3.x, q3.y); a[7] = pk2(q3.z, q3.w);

        ull accA = 0ull, accB = 0ull;
#pragma unroll
        for (int k2 = 0; k2 < 8; k2++) {
            ffma2(accA, a[k2], wA[k2]);
            ffma2(accB, a[k2], wB[k2]);
        }
        float aLo, aHi, bLo, bHi;
        upk2(aLo, aHi, accA);
        upk2(bLo, bHi, accB);
        acc0 += fmaxf(xv.x + (aLo + aHi + bev.x), 0.f);
        acc1 += fmaxf(xv.y + (bLo + bHi + bev.y), 0.f);

        er = ern; q0 = n0; q1 = n1; q2 = n2; q3 = n3;
        p = pn;
    }

    const float2 xn = *reinterpret_cast<const float2*>(x + (size_t)n * DIM + c0);
    *reinterpret_cast<float2*>(g_h + (size_t)n * DIM + c0) =
        make_float2(xn.x + acc0, xn.y + acc1);
}

// ---------------------------------------------------------------------------
// Phase C: out = relu(h@W1 + b1) @ W2 + b2   (unchanged from R2)
// ---------------------------------------------------------------------------
#define HS_LD 68
#define MLP_SMEM (128 * HS_LD * 4 + 32 * 64 * 8)

__global__ void __launch_bounds__(256) mlp_kernel(
    const float* __restrict__ W1, const float* __restrict__ b1,
    const float* __restrict__ W2, const float* __restrict__ b2,
    float* __restrict__ out, int N)
{
    extern __shared__ float smem[];
    float* hs = smem;
    ull*   Wp = reinterpret_cast<ull*>(smem + 128 * HS_LD);

    const int tid = threadIdx.x;
    const int nb = blockIdx.x * 128;

#pragma unroll
    for (int f = tid; f < 128 * 16; f += 256) {
        const int i = f >> 4, c4 = f & 15;
        float4 v = make_float4(0.f, 0.f, 0.f, 0.f);
        if (nb + i < N) v = reinterpret_cast<const float4*>(g_h)[(size_t)(nb + i) * 16 + c4];
        *reinterpret_cast<float4*>(hs + i * HS_LD + c4 * 4) = v;
    }
    for (int f = tid; f < 2048; f += 256) {
        const int k2 = f >> 6, j = f & 63;
        Wp[f] = pk2(W1[(2 * k2) * DIM + j], W1[(2 * k2 + 1) * DIM + j]);
    }
    __syncthreads();

    const int rg = tid >> 4, jg = tid & 15;
    const int i0 = rg * 8, j0 = jg * 4;
    float t[8][4];

    {
        ull acc[8][4];
#pragma unroll
        for (int ii = 0; ii < 8; ii++)
#pragma unroll
            for (int jj = 0; jj < 4; jj++) acc[ii][jj] = 0ull;
#pragma unroll 8
        for (int k2 = 0; k2 < 32; k2++) {
            ull hv[8];
#pragma unroll
            for (int ii = 0; ii < 8; ii++)
                hv[ii] = *reinterpret_cast<const ull*>(hs + (i0 + ii) * HS_LD + 2 * k2);
            const ulonglong2 w01 = *reinterpret_cast<const ulonglong2*>(Wp + k2 * 64 + j0);
            const ulonglong2 w23 = *reinterpret_cast<const ulonglong2*>(Wp + k2 * 64 + j0 + 2);
            ull wv[4] = { w01.x, w01.y, w23.x, w23.y };
#pragma unroll
            for (int ii = 0; ii < 8; ii++)
#pragma unroll
                for (int jj = 0; jj < 4; jj++) ffma2(acc[ii][jj], hv[ii], wv[jj]);
        }
        const float4 bb = *reinterpret_cast<const float4*>(b1 + j0);
        const float bbv[4] = { bb.x, bb.y, bb.z, bb.w };
#pragma unroll
        for (int ii = 0; ii < 8; ii++)
#pragma unroll
            for (int jj = 0; jj < 4; jj++) {
                float lo, hi;
                upk2(lo, hi, acc[ii][jj]);
                t[ii][jj] = fmaxf(lo + hi + bbv[jj], 0.f);
            }
    }
    __syncthreads();

#pragma unroll
    for (int ii = 0; ii < 8; ii++)
        *reinterpret_cast<float4*>(hs + (i0 + ii) * HS_LD + j0) =
            make_float4(t[ii][0], t[ii][1], t[ii][2], t[ii][3]);
    for (int f = tid; f < 2048; f += 256) {
        const int k2 = f >> 6, j = f & 63;
        Wp[f] = pk2(W2[(2 * k2) * DIM + j], W2[(2 * k2 + 1) * DIM + j]);
    }
    __syncthreads();

    {
        ull acc[8][4];
#pragma unroll
        for (int ii = 0; ii < 8; ii++)
#pragma unroll
            for (int jj = 0; jj < 4; jj++) acc[ii][jj] = 0ull;
#pragma unroll 8
        for (int k2 = 0; k2 < 32; k2++) {
            ull hv[8];
#pragma unroll
            for (int ii = 0; ii < 8; ii++)
                hv[ii] = *reinterpret_cast<const ull*>(hs + (i0 + ii) * HS_LD + 2 * k2);
            const ulonglong2 w01 = *reinterpret_cast<const ulonglong2*>(Wp + k2 * 64 + j0);
            const ulonglong2 w23 = *reinterpret_cast<const ulonglong2*>(Wp + k2 * 64 + j0 + 2);
            ull wv[4] = { w01.x, w01.y, w23.x, w23.y };
#pragma unroll
            for (int ii = 0; ii < 8; ii++)
#pragma unroll
                for (int jj = 0; jj < 4; jj++) ffma2(acc[ii][jj], hv[ii], wv[jj]);
        }
        const float4 bb = *reinterpret_cast<const float4*>(b2 + j0);
        const float bbv[4] = { bb.x, bb.y, bb.z, bb.w };
#pragma unroll
        for (int ii = 0; ii < 8; ii++) {
            const int n = nb + i0 + ii;
            if (n < N) {
                float r[4];
#pragma unroll
                for (int jj = 0; jj < 4; jj++) {
                    float lo, hi;
                    upk2(lo, hi, acc[ii][jj]);
                    r[jj] = lo + hi + bbv[jj];
                }
                *reinterpret_cast<float4*>(out + (size_t)n * DIM + j0) =
                    make_float4(r[0], r[1], r[2], r[3]);
            }
        }
    }
}

// ---------------------------------------------------------------------------
extern "C" void kernel_launch(void* const* d_in, const int* in_sizes, int n_in,
                              void* d_out, int out_size)
{
    const float* x  = (const float*)d_in[0];
    const int*   ei = (const int*)d_in[1];        // int32 (JAX x64 disabled)
    const float* ea = (const float*)d_in[2];
    const float* We = (const float*)d_in[3];
    const float* be = (const float*)d_in[4];
    const float* W1 = (const float*)d_in[5];
    const float* b1 = (const float*)d_in[6];
    const float* W2 = (const float*)d_in[7];
    const float* b2 = (const float*)d_in[8];
    float* out = (float*)d_out;

    const int N = in_sizes[0] / DIM;       // 100000
    const int E = in_sizes[1] / 2;         // 1600000

    const int nbN   = (N + 255) / 256;
    const int nbE   = (E + 255) / 256;
    const int nbScn = (N + SCAN_BS - 1) / SCAN_BS;   // 98

    // A) dst-bucket counting sort
    zero_cnt_kernel<<<nbN, 256>>>(N);
    hist_kernel<<<nbE, 256>>>(ei, E);
    scan1_kernel<<<nbScn, SCAN_BS>>>(N);
    scan2_kernel<<<1, 32>>>(nbScn);
    scan3_kernel<<<nbScn, SCAN_BS>>>(N, E);
    scatter_kernel<<<nbE, 256>>>(ei, E);

    // B) gather-side aggregation: one warp per node
    aggregate_kernel<<<(N * 32 + 255) / 256, 256>>>(
        x, reinterpret_cast<const float4*>(ea), We, be, N);

    // C) node MLP
    cudaFuncSetAttribute(mlp_kernel, cudaFuncAttributeMaxDynamicSharedMemorySize, MLP_SMEM);
    mlp_kernel<<<(N + 127) / 128, 256, MLP_SMEM>>>(W1, b1, W2, b2, out, N);
}

// round 4
// speedup vs baseline: 1.2709x; 1.2709x over previous
#include <cuda_runtime.h>

#define DIM 64
#define MAX_NODES 100000
#define MAX_EDGES 1600000
#define SCAN_BS 1024

typedef unsigned long long ull;

// ---- device scratch (no allocs allowed) ----
__device__ __align__(16) float g_h[MAX_NODES * DIM];     // h = x + aggr
__device__ int  g_cnt[MAX_NODES];                        // degree histogram
__device__ int  g_offpart[MAX_NODES];                    // per-block exclusive scan
__device__ int  g_bsum[128];                             // block sums for scan
__device__ int  g_off[MAX_NODES + 1];                    // final offsets
__device__ int  g_cur[MAX_NODES];                        // scatter cursors
__device__ __align__(8) int2 g_edges[MAX_EDGES];         // (src, edge_id) sorted by dst

__device__ __forceinline__ ull pk2(float lo, float hi) {
    ull r; asm("mov.b64 %0, {%1, %2};" : "=l"(r) : "f"(lo), "f"(hi)); return r;
}
__device__ __forceinline__ void upk2(float& lo, float& hi, ull v) {
    asm("mov.b64 {%0, %1}, %2;" : "=f"(lo), "=f"(hi) : "l"(v));
}
__device__ __forceinline__ void ffma2(ull& d, ull a, ull b) {
    asm("fma.rn.f32x2 %0, %1, %2, %0;" : "+l"(d) : "l"(a), "l"(b));
}

// ---------------------------------------------------------------------------
// Phase A: dst-bucket construction (counting sort, int atomics only)
// ---------------------------------------------------------------------------
__global__ void zero_cnt_kernel(int N) {
    int i = blockIdx.x * blockDim.x + threadIdx.x;
    if (i < N) g_cnt[i] = 0;
}

__global__ void hist_kernel(const int* __restrict__ ei, int E) {
    int e = blockIdx.x * blockDim.x + threadIdx.x;
    if (e < E) atomicAdd(&g_cnt[ei[E + e]], 1);
}

// per-block exclusive scan of counts; block total -> g_bsum
__global__ void __launch_bounds__(SCAN_BS) scan1_kernel(int N) {
    const int tid = threadIdx.x;
    const int lane = tid & 31, wid = tid >> 5;
    const int i = blockIdx.x * SCAN_BS + tid;
    int c = (i < N) ? g_cnt[i] : 0;

    int v = c;
#pragma unroll
    for (int d = 1; d < 32; d <<= 1) {
        int t = __shfl_up_sync(0xFFFFFFFFu, v, d);
        if (lane >= d) v += t;
    }
    __shared__ int ws[32];
    if (lane == 31) ws[wid] = v;
    __syncthreads();
    if (wid == 0) {
        int s = ws[lane];
#pragma unroll
        for (int d = 1; d < 32; d <<= 1) {
            int t = __shfl_up_sync(0xFFFFFFFFu, s, d);
            if (lane >= d) s += t;
        }
        ws[lane] = s;
    }
    __syncthreads();
    const int base = (wid > 0) ? ws[wid - 1] : 0;
    const int incl = v + base;
    if (i < N) g_offpart[i] = incl - c;
    if (tid == SCAN_BS - 1) g_bsum[blockIdx.x] = incl;
}

// parallel exclusive scan of <=128 block sums (one block, 128 threads)
__global__ void __launch_bounds__(128) scan2_kernel(int nb) {
    const int tid = threadIdx.x;
    const int lane = tid & 31, wid = tid >> 5;
    int c = (tid < nb) ? g_bsum[tid] : 0;
    int v = c;
#pragma unroll
    for (int d = 1; d < 32; d <<= 1) {
        int t = __shfl_up_sync(0xFFFFFFFFu, v, d);
        if (lane >= d) v += t;
    }
    __shared__ int ws[4];
    if (lane == 31) ws[wid] = v;
    __syncthreads();
    int base = 0;
#pragma unroll
    for (int w = 0; w < 4; w++) if (w < wid) base += ws[w];
    if (tid < nb) g_bsum[tid] = (v + base) - c;   // exclusive
}

// apply block offsets -> final offsets + cursors
__global__ void __launch_bounds__(SCAN_BS) scan3_kernel(int N, int E) {
    const int i = blockIdx.x * SCAN_BS + threadIdx.x;
    if (i < N) {
        const int o = g_offpart[i] + g_bsum[blockIdx.x];
        g_off[i] = o;
        g_cur[i] = o;
    }
    if (blockIdx.x == 0 && threadIdx.x == 0) g_off[N] = E;
}

__global__ void scatter_kernel(const int* __restrict__ ei, int E) {
    int e = blockIdx.x * blockDim.x + threadIdx.x;
    if (e < E) {
        const int dst = ei[E + e];
        const int p = atomicAdd(&g_cur[dst], 1);
        g_edges[p] = make_int2(ei[e], e);
    }
}

// ---------------------------------------------------------------------------
// Phase B: per-node aggregation. One warp per node, lane owns cols (2l, 2l+1).
// h[n] = x[n] + sum_{e: dst=n} relu(x[src_e] + ea_e @ We + be)
// TWO edges per loop iteration: all loads (records, 8x edge_attr float4,
// 2x x-gather) issue before any FMA -> ~10 independent loads in flight.
// ---------------------------------------------------------------------------
__global__ void __launch_bounds__(256, 2) aggregate_kernel(
    const float* __restrict__ x,
    const float4* __restrict__ ea4,     // [E, 16] as float4
    const float* __restrict__ We,       // [16, 64]
    const float* __restrict__ be,       // [64]
    int N)
{
    __shared__ ull Wp[8 * DIM];         // packed K-pairs of We: Wp[k2*64+j]
    const int tid = threadIdx.x;
    for (int f = tid; f < 8 * DIM; f += 256) {
        const int k2 = f >> 6, j = f & 63;
        Wp[f] = pk2(We[(2 * k2) * DIM + j], We[(2 * k2 + 1) * DIM + j]);
    }
    __syncthreads();

    const int lane = tid & 31;
    const int c0 = lane * 2;
    const int n = (blockIdx.x * blockDim.x + tid) >> 5;
    if (n >= N) return;

    ull wA[8], wB[8];
#pragma unroll
    for (int k2 = 0; k2 < 8; k2++) {
        wA[k2] = Wp[k2 * 64 + c0];
        wB[k2] = Wp[k2 * 64 + c0 + 1];
    }
    const float2 bev = *reinterpret_cast<const float2*>(be + c0);

    const int beg = g_off[n];
    const int end = g_off[n + 1];

    float acc0 = 0.f, acc1 = 0.f;

    int p = beg;
    // ---- main loop: 2 edges per iteration ----
    for (; p + 2 <= end; p += 2) {
        const int2 e0 = g_edges[p];
        const int2 e1 = g_edges[p + 1];

        const float4* a0p = ea4 + (size_t)e0.y * 4;
        const float4* a1p = ea4 + (size_t)e1.y * 4;
        const float4 q00 = a0p[0], q01 = a0p[1], q02 = a0p[2], q03 = a0p[3];
        const float4 q10 = a1p[0], q11 = a1p[1], q12 = a1p[2], q13 = a1p[3];

        const float2 xv0 = *reinterpret_cast<const float2*>(x + (size_t)e0.x * DIM + c0);
        const float2 xv1 = *reinterpret_cast<const float2*>(x + (size_t)e1.x * DIM + c0);

        ull a0[8], a1[8];
        a0[0] = pk2(q00.x, q00.y); a0[1] = pk2(q00.z, q00.w);
        a0[2] = pk2(q01.x, q01.y); a0[3] = pk2(q01.z, q01.w);
        a0[4] = pk2(q02.x, q02.y); a0[5] = pk2(q02.z, q02.w);
        a0[6] = pk2(q03.x, q03.y); a0[7] = pk2(q03.z, q03.w);
        a1[0] = pk2(q10.x, q10.y); a1[1] = pk2(q10.z, q10.w);
        a1[2] = pk2(q11.x, q11.y); a1[3] = pk2(q11.z, q11.w);
        a1[4] = pk2(q12.x, q12.y); a1[5] = pk2(q12.z, q12.w);
        a1[6] = pk2(q13.x, q13.y); a1[7] = pk2(q13.z, q13.w);

        ull A0 = 0ull, B0 = 0ull, A1 = 0ull, B1 = 0ull;
#pragma unroll
        for (int k2 = 0; k2 < 8; k2++) {
            ffma2(A0, a0[k2], wA[k2]);
            ffma2(A1, a1[k2], wA[k2]);
            ffma2(B0, a0[k2], wB[k2]);
            ffma2(B1, a1[k2], wB[k2]);
        }
        float l0, h0, l1, h1, l2, h2, l3, h3;
        upk2(l0, h0, A0); upk2(l1, h1, B0);
        upk2(l2, h2, A1); upk2(l3, h3, B1);
        acc0 += fmaxf(xv0.x + (l0 + h0 + bev.x), 0.f)
              + fmaxf(xv1.x + (l2 + h2 + bev.x), 0.f);
        acc1 += fmaxf(xv0.y + (l1 + h1 + bev.y), 0.f)
              + fmaxf(xv1.y + (l3 + h3 + bev.y), 0.f);
    }
    // ---- remainder edge ----
    if (p < end) {
        const int2 e0 = g_edges[p];
        const float4* a0p = ea4 + (size_t)e0.y * 4;
        const float4 q00 = a0p[0], q01 = a0p[1], q02 = a0p[2], q03 = a0p[3];
        const float2 xv0 = *reinterpret_cast<const float2*>(x + (size_t)e0.x * DIM + c0);

        ull a0[8];
        a0[0] = pk2(q00.x, q00.y); a0[1] = pk2(q00.z, q00.w);
        a0[2] = pk2(q01.x, q01.y); a0[3] = pk2(q01.z, q01.w);
        a0[4] = pk2(q02.x, q02.y); a0[5] = pk2(q02.z, q02.w);
        a0[6] = pk2(q03.x, q03.y); a0[7] = pk2(q03.z, q03.w);

        ull A0 = 0ull, B0 = 0ull;
#pragma unroll
        for (int k2 = 0; k2 < 8; k2++) {
            ffma2(A0, a0[k2], wA[k2]);
            ffma2(B0, a0[k2], wB[k2]);
        }
        float l0, h0, l1, h1;
        upk2(l0, h0, A0); upk2(l1, h1, B0);
        acc0 += fmaxf(xv0.x + (l0 + h0 + bev.x), 0.f);
        acc1 += fmaxf(xv0.y + (l1 + h1 + bev.y), 0.f);
    }

    const float2 xn = *reinterpret_cast<const float2*>(x + (size_t)n * DIM + c0);
    *reinterpret_cast<float2*>(g_h + (size_t)n * DIM + c0) =
        make_float2(xn.x + acc0, xn.y + acc1);
}

// ---------------------------------------------------------------------------
// Phase C: out = relu(h@W1 + b1) @ W2 + b2
// ---------------------------------------------------------------------------
#define HS_LD 68
#define MLP_SMEM (128 * HS_LD * 4 + 32 * 64 * 8)

__global__ void __launch_bounds__(256) mlp_kernel(
    const float* __restrict__ W1, const float* __restrict__ b1,
    const float* __restrict__ W2, const float* __restrict__ b2,
    float* __restrict__ out, int N)
{
    extern __shared__ float smem[];
    float* hs = smem;
    ull*   Wp = reinterpret_cast<ull*>(smem + 128 * HS_LD);

    const int tid = threadIdx.x;
    const int nb = blockIdx.x * 128;

#pragma unroll
    for (int f = tid; f < 128 * 16; f += 256) {
        const int i = f >> 4, c4 = f & 15;
        float4 v = make_float4(0.f, 0.f, 0.f, 0.f);
        if (nb + i < N) v = reinterpret_cast<const float4*>(g_h)[(size_t)(nb + i) * 16 + c4];
        *reinterpret_cast<float4*>(hs + i * HS_LD + c4 * 4) = v;
    }
    for (int f = tid; f < 2048; f += 256) {
        const int k2 = f >> 6, j = f & 63;
        Wp[f] = pk2(W1[(2 * k2) * DIM + j], W1[(2 * k2 + 1) * DIM + j]);
    }
    __syncthreads();

    const int rg = tid >> 4, jg = tid & 15;
    const int i0 = rg * 8, j0 = jg * 4;
    float t[8][4];

    {
        ull acc[8][4];
#pragma unroll
        for (int ii = 0; ii < 8; ii++)
#pragma unroll
            for (int jj = 0; jj < 4; jj++) acc[ii][jj] = 0ull;
#pragma unroll 8
        for (int k2 = 0; k2 < 32; k2++) {
            ull hv[8];
#pragma unroll
            for (int ii = 0; ii < 8; ii++)
                hv[ii] = *reinterpret_cast<const ull*>(hs + (i0 + ii) * HS_LD + 2 * k2);
            const ulonglong2 w01 = *reinterpret_cast<const ulonglong2*>(Wp + k2 * 64 + j0);
            const ulonglong2 w23 = *reinterpret_cast<const ulonglong2*>(Wp + k2 * 64 + j0 + 2);
            ull wv[4] = { w01.x, w01.y, w23.x, w23.y };
#pragma unroll
            for (int ii = 0; ii < 8; ii++)
#pragma unroll
                for (int jj = 0; jj < 4; jj++) ffma2(acc[ii][jj], hv[ii], wv[jj]);
        }
        const float4 bb = *reinterpret_cast<const float4*>(b1 + j0);
        const float bbv[4] = { bb.x, bb.y, bb.z, bb.w };
#pragma unroll
        for (int ii = 0; ii < 8; ii++)
#pragma unroll
            for (int jj = 0; jj < 4; jj++) {
                float lo, hi;
                upk2(lo, hi, acc[ii][jj]);
                t[ii][jj] = fmaxf(lo + hi + bbv[jj], 0.f);
            }
    }
    __syncthreads();

#pragma unroll
    for (int ii = 0; ii < 8; ii++)
        *reinterpret_cast<float4*>(hs + (i0 + ii) * HS_LD + j0) =
            make_float4(t[ii][0], t[ii][1], t[ii][2], t[ii][3]);
    for (int f = tid; f < 2048; f += 256) {
        const int k2 = f >> 6, j = f & 63;
        Wp[f] = pk2(W2[(2 * k2) * DIM + j], W2[(2 * k2 + 1) * DIM + j]);
    }
    __syncthreads();

    {
        ull acc[8][4];
#pragma unroll
        for (int ii = 0; ii < 8; ii++)
#pragma unroll
            for (int jj = 0; jj < 4; jj++) acc[ii][jj] = 0ull;
#pragma unroll 8
        for (int k2 = 0; k2 < 32; k2++) {
            ull hv[8];
#pragma unroll
            for (int ii = 0; ii < 8; ii++)
                hv[ii] = *reinterpret_cast<const ull*>(hs + (i0 + ii) * HS_LD + 2 * k2);
            const ulonglong2 w01 = *reinterpret_cast<const ulonglong2*>(Wp + k2 * 64 + j0);
            const ulonglong2 w23 = *reinterpret_cast<const ulonglong2*>(Wp + k2 * 64 + j0 + 2);
            ull wv[4] = { w01.x, w01.y, w23.x, w23.y };
#pragma unroll
            for (int ii = 0; ii < 8; ii++)
#pragma unroll
                for (int jj = 0; jj < 4; jj++) ffma2(acc[ii][jj], hv[ii], wv[jj]);
        }
        const float4 bb = *reinterpret_cast<const float4*>(b2 + j0);
        const float bbv[4] = { bb.x, bb.y, bb.z, bb.w };
#pragma unroll
        for (int ii = 0; ii < 8; ii++) {
            const int n = nb + i0 + ii;
            if (n < N) {
                float r[4];
#pragma unroll
                for (int jj = 0; jj < 4; jj++) {
                    float lo, hi;
                    upk2(lo, hi, acc[ii][jj]);
                    r[jj] = lo + hi + bbv[jj];
                }
                *reinterpret_cast<float4*>(out + (size_t)n * DIM + j0) =
                    make_float4(r[0], r[1], r[2], r[3]);
            }
        }
    }
}

// ---------------------------------------------------------------------------
extern "C" void kernel_launch(void* const* d_in, const int* in_sizes, int n_in,
                              void* d_out, int out_size)
{
    const float* x  = (const float*)d_in[0];
    const int*   ei = (const int*)d_in[1];        // int32 (JAX x64 disabled)
    const float* ea = (const float*)d_in[2];
    const float* We = (const float*)d_in[3];
    const float* be = (const float*)d_in[4];
    const float* W1 = (const float*)d_in[5];
    const float* b1 = (const float*)d_in[6];
    const float* W2 = (const float*)d_in[7];
    const float* b2 = (const float*)d_in[8];
    float* out = (float*)d_out;

    const int N = in_sizes[0] / DIM;       // 100000
    const int E = in_sizes[1] / 2;         // 1600000

    const int nbN   = (N + 255) / 256;
    const int nbE   = (E + 255) / 256;
    const int nbScn = (N + SCAN_BS - 1) / SCAN_BS;   // 98 (<=128)

    // A) dst-bucket counting sort
    zero_cnt_kernel<<<nbN, 256>>>(N);
    hist_kernel<<<nbE, 256>>>(ei, E);
    scan1_kernel<<<nbScn, SCAN_BS>>>(N);
    scan2_kernel<<<1, 128>>>(nbScn);
    scan3_kernel<<<nbScn, SCAN_BS>>>(N, E);
    scatter_kernel<<<nbE, 256>>>(ei, E);

    // B) gather-side aggregation: one warp per node, 2-edge ILP
    aggregate_kernel<<<(N * 32 + 255) / 256, 256>>>(
        x, reinterpret_cast<const float4*>(ea), We, be, N);

    // C) node MLP
    cudaFuncSetAttribute(mlp_kernel, cudaFuncAttributeMaxDynamicSharedMemorySize, MLP_SMEM);
    mlp_kernel<<<(N + 127) / 128, 256, MLP_SMEM>>>(W1, b1, W2, b2, out, N);
}